// round 6
// baseline (speedup 1.0000x reference)
#include <cuda_runtime.h>

// Problem constants (fixed by the dataset)
#define NMAX 50000
#define EMAX 640000

// Scratch (allocation-free rule: __device__ globals)
__device__ int   g_count[NMAX];         // out-degree counts (by src)
__device__ float g_dinv[NMAX];          // weighted in-degree (incl self) -> rsqrt
__device__ int   g_offsets[NMAX + 1];   // sorted-edge row offsets (by src)
__device__ int   g_cursor[NMAX];        // fill cursors
__device__ int   g_ssrc[EMAX];          // src, sorted by src
__device__ int   g_sdst[EMAX];          // dst, sorted by src
__device__ float g_snorm[EMAX];         // norm, sorted by src
__device__ float g_h[NMAX * 128];       // GEMM output (pre-aggregation)
__device__ float g_agg[NMAX * 128];     // aggregation buffer (init + scatter)
__device__ float g_h3[NMAX * 40];       // layer-3 GEMM output

// ---------------------------------------------------------------------------
// Edge sort (by src) + degree normalization (by dst)
// ---------------------------------------------------------------------------
__global__ void zero_kernel(int* count, float* deg, int n) {
    int i = blockIdx.x * blockDim.x + threadIdx.x;
    if (i < n) { count[i] = 0; deg[i] = 1.0f; }  // self-loop weight
}

__global__ void hist_kernel(const int* __restrict__ src,
                            const int* __restrict__ dst,
                            const float* __restrict__ ew,
                            int* __restrict__ count,
                            float* __restrict__ deg, int e) {
    int i = blockIdx.x * blockDim.x + threadIdx.x;
    if (i < e) {
        atomicAdd(count + src[i], 1);
        atomicAdd(deg + dst[i], ew[i]);
    }
}

// Single-block exclusive scan of count[n] -> offsets/cursor; deg -> rsqrt(deg).
__global__ void __launch_bounds__(1024)
scan_kernel(const int* __restrict__ count,
            float* __restrict__ deg_dinv,
            int* __restrict__ offsets,
            int* __restrict__ cursor, int n) {
    __shared__ int part[1024];
    const int t = threadIdx.x;
    const int C = (n + 1023) / 1024;
    const int base = t * C;

    int sum = 0;
    for (int i = 0; i < C; i++) {
        int idx = base + i;
        sum += (idx < n) ? count[idx] : 0;
    }
    part[t] = sum;
    __syncthreads();
    for (int off = 1; off < 1024; off <<= 1) {
        int v = (t >= off) ? part[t - off] : 0;
        __syncthreads();
        part[t] += v;
        __syncthreads();
    }
    int run = (t > 0) ? part[t - 1] : 0;
    for (int i = 0; i < C; i++) {
        int idx = base + i;
        if (idx < n) {
            offsets[idx] = run;
            cursor[idx] = run;
            run += count[idx];
        }
    }
    if (t == 1023) offsets[n] = part[1023];

    for (int i = t; i < n; i += 1024) deg_dinv[i] = rsqrtf(deg_dinv[i]);
}

__global__ void fill_kernel(const int* __restrict__ src,
                            const int* __restrict__ dst,
                            const float* __restrict__ ew,
                            const float* __restrict__ dinv,
                            int* __restrict__ cursor,
                            int* __restrict__ s_src,
                            int* __restrict__ s_dst,
                            float* __restrict__ s_norm, int e) {
    int i = blockIdx.x * blockDim.x + threadIdx.x;
    if (i >= e) return;
    int s = src[i];
    int d = dst[i];
    int pos = atomicAdd(cursor + s, 1);
    s_src[pos] = s;
    s_dst[pos] = d;
    s_norm[pos] = dinv[s] * ew[i] * dinv[d];
}

// ---------------------------------------------------------------------------
// GEMM: [n,128] @ [128,128] -> writes H (raw) and AGG init = H*dinv^2 + bias
// (round-1 proven kernel) Optional ReLU on the A operand.
// ---------------------------------------------------------------------------
template <bool RELU_IN>
__global__ void __launch_bounds__(256, 2)
gemm128_kernel(const float* __restrict__ A,
               const float* __restrict__ W,
               const float* __restrict__ bias,
               const float* __restrict__ dinv,
               float* __restrict__ Hout,
               float* __restrict__ AggOut,
               int n) {
    __shared__ float As[16][128];  // transposed: As[k][m]
    __shared__ float Bs[16][128];  // Bs[k][n]

    const int tid = threadIdx.x;
    const int tx = tid & 15;
    const int ty = tid >> 4;
    const int rb = blockIdx.x * 128;

    float acc[8][8];
#pragma unroll
    for (int i = 0; i < 8; i++)
#pragma unroll
        for (int j = 0; j < 8; j++) acc[i][j] = 0.0f;

    for (int k0 = 0; k0 < 128; k0 += 16) {
#pragma unroll
        for (int l = 0; l < 2; l++) {
            int f = tid + l * 256;
            int row = f >> 2;
            int c4 = (f & 3) * 4;
            float4 v = make_float4(0.f, 0.f, 0.f, 0.f);
            int gr = rb + row;
            if (gr < n) v = *(const float4*)(A + (size_t)gr * 128 + k0 + c4);
            if (RELU_IN) {
                v.x = fmaxf(v.x, 0.f); v.y = fmaxf(v.y, 0.f);
                v.z = fmaxf(v.z, 0.f); v.w = fmaxf(v.w, 0.f);
            }
            As[c4 + 0][row] = v.x;
            As[c4 + 1][row] = v.y;
            As[c4 + 2][row] = v.z;
            As[c4 + 3][row] = v.w;
        }
#pragma unroll
        for (int l = 0; l < 2; l++) {
            int f = tid + l * 256;
            int kr = f >> 5;
            int c = (f & 31) * 4;
            *(float4*)&Bs[kr][c] = *(const float4*)(W + (size_t)(k0 + kr) * 128 + c);
        }
        __syncthreads();

#pragma unroll
        for (int k = 0; k < 16; k++) {
            float4 a0 = *(const float4*)&As[k][ty * 8];
            float4 a1 = *(const float4*)&As[k][ty * 8 + 4];
            float4 b0 = *(const float4*)&Bs[k][tx * 8];
            float4 b1 = *(const float4*)&Bs[k][tx * 8 + 4];
            float a[8] = {a0.x, a0.y, a0.z, a0.w, a1.x, a1.y, a1.z, a1.w};
            float b[8] = {b0.x, b0.y, b0.z, b0.w, b1.x, b1.y, b1.z, b1.w};
#pragma unroll
            for (int i = 0; i < 8; i++)
#pragma unroll
                for (int j = 0; j < 8; j++)
                    acc[i][j] = fmaf(a[i], b[j], acc[i][j]);
        }
        __syncthreads();
    }

#pragma unroll
    for (int i = 0; i < 8; i++) {
        int row = rb + ty * 8 + i;
        if (row >= n) break;
        float sl = dinv[row];
        sl = sl * sl;
#pragma unroll
        for (int j = 0; j < 8; j += 4) {
            int col = tx * 8 + j;
            float4 hv = make_float4(acc[i][j], acc[i][j + 1], acc[i][j + 2], acc[i][j + 3]);
            *(float4*)(Hout + (size_t)row * 128 + col) = hv;
            float4 bv = *(const float4*)(bias + col);
            float4 av;
            av.x = fmaf(hv.x, sl, bv.x);
            av.y = fmaf(hv.y, sl, bv.y);
            av.z = fmaf(hv.z, sl, bv.z);
            av.w = fmaf(hv.w, sl, bv.w);
            *(float4*)(AggOut + (size_t)row * 128 + col) = av;
        }
    }
}

// ---------------------------------------------------------------------------
// Sorted-edge scatter (128 feats): one warp per edge; src-sorted order means
// consecutive warps share the same h row -> L1 hits on the gather.
// ---------------------------------------------------------------------------
__global__ void __launch_bounds__(256)
scatter128_kernel(const float* __restrict__ h,
                  const int* __restrict__ s_src,
                  const int* __restrict__ s_dst,
                  const float* __restrict__ s_norm,
                  float* __restrict__ agg,
                  int e) {
    int warp = (blockIdx.x * blockDim.x + threadIdx.x) >> 5;
    int lane = threadIdx.x & 31;
    if (warp >= e) return;
    int s = s_src[warp];
    int d = s_dst[warp];
    float nm = s_norm[warp];
    float4 v = *(const float4*)(h + (size_t)s * 128 + lane * 4);
    float rx = v.x * nm, ry = v.y * nm, rz = v.z * nm, rw = v.w * nm;
    float* p = agg + (size_t)d * 128 + lane * 4;
    asm volatile("red.global.add.v4.f32 [%0], {%1, %2, %3, %4};"
                 :: "l"(p), "f"(rx), "f"(ry), "f"(rz), "f"(rw)
                 : "memory");
}

// ---------------------------------------------------------------------------
// Layer-3 GEMM: relu(A)[n,128] @ [128,40] -> H3 and Out init (round-1 proven)
// ---------------------------------------------------------------------------
__global__ void __launch_bounds__(128)
gemm40_kernel(const float* __restrict__ A,
              const float* __restrict__ W,
              const float* __restrict__ bias,
              const float* __restrict__ dinv,
              float* __restrict__ Hout,
              float* __restrict__ Out,
              int n) {
    extern __shared__ float sm[];
    float* xs = sm;                 // 64 rows, stride 129
    float* ws = sm + 64 * 129;      // 128*40 flat

    const int tid = threadIdx.x;
    const int rb = blockIdx.x * 64;

    for (int l = tid * 4; l < 128 * 40; l += 128 * 4)
        *(float4*)(ws + l) = *(const float4*)(W + l);

    for (int f = tid; f < 2048; f += 128) {
        int row = f >> 5;
        int c = (f & 31) * 4;
        float4 v = make_float4(0.f, 0.f, 0.f, 0.f);
        int gr = rb + row;
        if (gr < n) v = *(const float4*)(A + (size_t)gr * 128 + c);
        float* xr = xs + row * 129 + c;
        xr[0] = fmaxf(v.x, 0.f);
        xr[1] = fmaxf(v.y, 0.f);
        xr[2] = fmaxf(v.z, 0.f);
        xr[3] = fmaxf(v.w, 0.f);
    }
    __syncthreads();

    const int tc = tid & 7;
    const int tr = tid >> 3;
    float acc[4][5];
#pragma unroll
    for (int r = 0; r < 4; r++)
#pragma unroll
        for (int j = 0; j < 5; j++) acc[r][j] = 0.0f;

#pragma unroll 4
    for (int k = 0; k < 128; k++) {
        float w[5];
#pragma unroll
        for (int j = 0; j < 5; j++) w[j] = ws[k * 40 + tc + 8 * j];
#pragma unroll
        for (int r = 0; r < 4; r++) {
            float a = xs[(tr * 4 + r) * 129 + k];
#pragma unroll
            for (int j = 0; j < 5; j++) acc[r][j] = fmaf(a, w[j], acc[r][j]);
        }
    }

#pragma unroll
    for (int r = 0; r < 4; r++) {
        int row = rb + tr * 4 + r;
        if (row >= n) break;
        float sl = dinv[row];
        sl = sl * sl;
#pragma unroll
        for (int j = 0; j < 5; j++) {
            int c = tc + 8 * j;
            float v = acc[r][j];
            Hout[(size_t)row * 40 + c] = v;
            Out[(size_t)row * 40 + c] = fmaf(v, sl, bias[c]);
        }
    }
}

// ---------------------------------------------------------------------------
// Sorted-edge scatter (40 feats): thread per (edge, 16B chunk); consecutive
// threads share the same edge/row -> coalesced + L1 reuse across edges.
// ---------------------------------------------------------------------------
__global__ void __launch_bounds__(256)
scatter40_kernel(const float* __restrict__ h,
                 const int* __restrict__ s_src,
                 const int* __restrict__ s_dst,
                 const float* __restrict__ s_norm,
                 float* __restrict__ out,
                 int e) {
    long long idx = (long long)blockIdx.x * blockDim.x + threadIdx.x;
    long long total = (long long)e * 10;
    if (idx >= total) return;
    int ed = (int)(idx / 10);
    int c = (int)(idx - (long long)ed * 10);
    int s = s_src[ed];
    int d = s_dst[ed];
    float nm = s_norm[ed];
    float4 v = *(const float4*)(h + (size_t)s * 40 + c * 4);
    float rx = v.x * nm, ry = v.y * nm, rz = v.z * nm, rw = v.w * nm;
    float* p = out + (size_t)d * 40 + c * 4;
    asm volatile("red.global.add.v4.f32 [%0], {%1, %2, %3, %4};"
                 :: "l"(p), "f"(rx), "f"(ry), "f"(rz), "f"(rw)
                 : "memory");
}

// ---------------------------------------------------------------------------
// Launch
// ---------------------------------------------------------------------------
extern "C" void kernel_launch(void* const* d_in, const int* in_sizes, int n_in,
                              void* d_out, int out_size) {
    const float* x  = (const float*)d_in[0];
    const int*   ei = (const int*)d_in[1];
    const float* ew = (const float*)d_in[2];
    const float* W1 = (const float*)d_in[3];
    const float* b1 = (const float*)d_in[4];
    const float* W2 = (const float*)d_in[5];
    const float* b2 = (const float*)d_in[6];
    const float* W3 = (const float*)d_in[7];
    const float* b3 = (const float*)d_in[8];
    float* out = (float*)d_out;

    const int n = in_sizes[0] / 128;       // 50000
    const int e = in_sizes[2];             // 640000
    const int* src = ei;
    const int* dst = ei + e;

    int *count, *offsets, *cursor, *ssrc, *sdst;
    float *dinv, *snorm, *h, *agg, *h3;
    cudaGetSymbolAddress((void**)&count,   g_count);
    cudaGetSymbolAddress((void**)&dinv,    g_dinv);
    cudaGetSymbolAddress((void**)&offsets, g_offsets);
    cudaGetSymbolAddress((void**)&cursor,  g_cursor);
    cudaGetSymbolAddress((void**)&ssrc,    g_ssrc);
    cudaGetSymbolAddress((void**)&sdst,    g_sdst);
    cudaGetSymbolAddress((void**)&snorm,   g_snorm);
    cudaGetSymbolAddress((void**)&h,       g_h);
    cudaGetSymbolAddress((void**)&agg,     g_agg);
    cudaGetSymbolAddress((void**)&h3,      g_h3);

    const int nb_n = (n + 255) / 256;
    const int nb_e = (e + 255) / 256;

    // Edge sort (by src) + dinv
    zero_kernel<<<nb_n, 256>>>(count, dinv, n);
    hist_kernel<<<nb_e, 256>>>(src, dst, ew, count, dinv, e);
    scan_kernel<<<1, 1024>>>(count, dinv, offsets, cursor, n);
    fill_kernel<<<nb_e, 256>>>(src, dst, ew, dinv, cursor, ssrc, sdst, snorm, e);

    const int gemm_blocks = (n + 127) / 128;
    const int scat_blocks = (e * 32 + 255) / 256;   // one warp per edge

    // Layer 1
    gemm128_kernel<false><<<gemm_blocks, 256>>>(x, W1, b1, dinv, h, agg, n);
    scatter128_kernel<<<scat_blocks, 256>>>(h, ssrc, sdst, snorm, agg, e);

    // Layer 2 (relu fused into GEMM A-load; in-place agg safe: block-local rows)
    gemm128_kernel<true><<<gemm_blocks, 256>>>(agg, W2, b2, dinv, h, agg, n);
    scatter128_kernel<<<scat_blocks, 256>>>(h, ssrc, sdst, snorm, agg, e);

    // Layer 3 (relu fused; output written directly to d_out)
    static const int g40_smem = (64 * 129 + 128 * 40) * sizeof(float);
    cudaFuncSetAttribute(gemm40_kernel,
                         cudaFuncAttributeMaxDynamicSharedMemorySize, g40_smem);
    gemm40_kernel<<<(n + 63) / 64, 128, g40_smem>>>(agg, W3, b3, dinv, h3, out, n);

    long long s40_threads = (long long)e * 10;
    int s40_blocks = (int)((s40_threads + 255) / 256);
    scatter40_kernel<<<s40_blocks, 256>>>(h3, ssrc, sdst, snorm, out, e);
}

// round 7
// speedup vs baseline: 1.1096x; 1.1096x over previous
#include <cuda_runtime.h>

// Problem constants (fixed by the dataset)
#define NMAX 50000
#define EMAX 640000
#define GRP 8

// Scratch (allocation-free rule: __device__ globals)
__device__ int   g_count[NMAX];         // in-degree counts (by dst)
__device__ float g_dinv[NMAX];          // weighted in-degree (incl self) -> rsqrt
__device__ int   g_offsets[NMAX + 1];   // sorted-edge row offsets (by dst)
__device__ int   g_cursor[NMAX];        // fill cursors
__device__ int4  g_pack[EMAX];          // {src, dst, norm_bits, 0}, sorted by dst
__device__ float g_h[NMAX * 128];       // GEMM output (pre-aggregation)
__device__ float g_agg[NMAX * 128];     // aggregation buffer (init + scatter)
__device__ float g_h3[NMAX * 40];       // layer-3 GEMM output

__device__ __forceinline__ void red4(float* p, float a, float b, float c, float d) {
    asm volatile("red.global.add.v4.f32 [%0], {%1, %2, %3, %4};"
                 :: "l"(p), "f"(a), "f"(b), "f"(c), "f"(d) : "memory");
}

// ---------------------------------------------------------------------------
// Preamble: histogram + weighted degree (both by dst)
// ---------------------------------------------------------------------------
__global__ void zero_kernel(int* count, float* deg, int n) {
    int i = blockIdx.x * blockDim.x + threadIdx.x;
    if (i < n) { count[i] = 0; deg[i] = 1.0f; }  // self-loop weight
}

__global__ void hist_kernel(const int* __restrict__ dst,
                            const float* __restrict__ ew,
                            int* __restrict__ count,
                            float* __restrict__ deg, int e) {
    int i = blockIdx.x * blockDim.x + threadIdx.x;
    if (i < e) {
        int d = dst[i];
        atomicAdd(count + d, 1);
        atomicAdd(deg + d, ew[i]);
    }
}

// Single-block exclusive scan of count[n] -> offsets/cursor; deg -> rsqrt(deg).
__global__ void __launch_bounds__(1024)
scan_kernel(const int* __restrict__ count,
            float* __restrict__ deg_dinv,
            int* __restrict__ offsets,
            int* __restrict__ cursor, int n) {
    __shared__ int part[1024];
    const int t = threadIdx.x;
    const int C = (n + 1023) / 1024;
    const int base = t * C;

    int sum = 0;
    for (int i = 0; i < C; i++) {
        int idx = base + i;
        sum += (idx < n) ? count[idx] : 0;
    }
    part[t] = sum;
    __syncthreads();
    for (int off = 1; off < 1024; off <<= 1) {
        int v = (t >= off) ? part[t - off] : 0;
        __syncthreads();
        part[t] += v;
        __syncthreads();
    }
    int run = (t > 0) ? part[t - 1] : 0;
    for (int i = 0; i < C; i++) {
        int idx = base + i;
        if (idx < n) {
            offsets[idx] = run;
            cursor[idx] = run;
            run += count[idx];
        }
    }
    if (t == 1023) offsets[n] = part[1023];

    for (int i = t; i < n; i += 1024) deg_dinv[i] = rsqrtf(deg_dinv[i]);
}

// Sort-by-dst fill; norm computed here (folds old norm_kernel).
__global__ void fill_kernel(const int* __restrict__ src,
                            const int* __restrict__ dst,
                            const float* __restrict__ ew,
                            const float* __restrict__ dinv,
                            int* __restrict__ cursor,
                            int4* __restrict__ pack, int e) {
    int i = blockIdx.x * blockDim.x + threadIdx.x;
    if (i >= e) return;
    int s = src[i];
    int d = dst[i];
    int pos = atomicAdd(cursor + d, 1);
    int4 p;
    p.x = s;
    p.y = d;
    p.z = __float_as_int(dinv[s] * ew[i] * dinv[d]);
    p.w = 0;
    pack[pos] = p;
}

// ---------------------------------------------------------------------------
// GEMM: [n,128] @ [128,128] -> writes H (raw) and AGG init = H*dinv^2 + bias
// (round-1 proven kernel) Optional ReLU on the A operand.
// ---------------------------------------------------------------------------
template <bool RELU_IN>
__global__ void __launch_bounds__(256, 2)
gemm128_kernel(const float* __restrict__ A,
               const float* __restrict__ W,
               const float* __restrict__ bias,
               const float* __restrict__ dinv,
               float* __restrict__ Hout,
               float* __restrict__ AggOut,
               int n) {
    __shared__ float As[16][128];  // transposed: As[k][m]
    __shared__ float Bs[16][128];  // Bs[k][n]

    const int tid = threadIdx.x;
    const int tx = tid & 15;
    const int ty = tid >> 4;
    const int rb = blockIdx.x * 128;

    float acc[8][8];
#pragma unroll
    for (int i = 0; i < 8; i++)
#pragma unroll
        for (int j = 0; j < 8; j++) acc[i][j] = 0.0f;

    for (int k0 = 0; k0 < 128; k0 += 16) {
#pragma unroll
        for (int l = 0; l < 2; l++) {
            int f = tid + l * 256;
            int row = f >> 2;
            int c4 = (f & 3) * 4;
            float4 v = make_float4(0.f, 0.f, 0.f, 0.f);
            int gr = rb + row;
            if (gr < n) v = *(const float4*)(A + (size_t)gr * 128 + k0 + c4);
            if (RELU_IN) {
                v.x = fmaxf(v.x, 0.f); v.y = fmaxf(v.y, 0.f);
                v.z = fmaxf(v.z, 0.f); v.w = fmaxf(v.w, 0.f);
            }
            As[c4 + 0][row] = v.x;
            As[c4 + 1][row] = v.y;
            As[c4 + 2][row] = v.z;
            As[c4 + 3][row] = v.w;
        }
#pragma unroll
        for (int l = 0; l < 2; l++) {
            int f = tid + l * 256;
            int kr = f >> 5;
            int c = (f & 31) * 4;
            *(float4*)&Bs[kr][c] = *(const float4*)(W + (size_t)(k0 + kr) * 128 + c);
        }
        __syncthreads();

#pragma unroll
        for (int k = 0; k < 16; k++) {
            float4 a0 = *(const float4*)&As[k][ty * 8];
            float4 a1 = *(const float4*)&As[k][ty * 8 + 4];
            float4 b0 = *(const float4*)&Bs[k][tx * 8];
            float4 b1 = *(const float4*)&Bs[k][tx * 8 + 4];
            float a[8] = {a0.x, a0.y, a0.z, a0.w, a1.x, a1.y, a1.z, a1.w};
            float b[8] = {b0.x, b0.y, b0.z, b0.w, b1.x, b1.y, b1.z, b1.w};
#pragma unroll
            for (int i = 0; i < 8; i++)
#pragma unroll
                for (int j = 0; j < 8; j++)
                    acc[i][j] = fmaf(a[i], b[j], acc[i][j]);
        }
        __syncthreads();
    }

#pragma unroll
    for (int i = 0; i < 8; i++) {
        int row = rb + ty * 8 + i;
        if (row >= n) break;
        float sl = dinv[row];
        sl = sl * sl;
#pragma unroll
        for (int j = 0; j < 8; j += 4) {
            int col = tx * 8 + j;
            float4 hv = make_float4(acc[i][j], acc[i][j + 1], acc[i][j + 2], acc[i][j + 3]);
            *(float4*)(Hout + (size_t)row * 128 + col) = hv;
            float4 bv = *(const float4*)(bias + col);
            float4 av;
            av.x = fmaf(hv.x, sl, bv.x);
            av.y = fmaf(hv.y, sl, bv.y);
            av.z = fmaf(hv.z, sl, bv.z);
            av.w = fmaf(hv.w, sl, bv.w);
            *(float4*)(AggOut + (size_t)row * 128 + col) = av;
        }
    }
}

// ---------------------------------------------------------------------------
// Segment-combining scatter (128 feats): one warp per GRP=8 dst-sorted edges.
// Srcs random -> high read MLP; same-dst runs combined in registers so reds
// drop ~5x (REDG-issue was the binding constraint).
// ---------------------------------------------------------------------------
__global__ void __launch_bounds__(256)
scatter128_grp(const float* __restrict__ h,
               const int4* __restrict__ pack,
               float* __restrict__ agg, int e) {
    int w = (blockIdx.x * blockDim.x + threadIdx.x) >> 5;
    int lane = threadIdx.x & 31;
    int base = w * GRP;
    if (base >= e) return;
    int cnt = min(GRP, e - base);

    int4 p[GRP];
#pragma unroll
    for (int g = 0; g < GRP; g++)
        if (g < cnt) p[g] = pack[base + g];

    float4 m[GRP];
#pragma unroll
    for (int g = 0; g < GRP; g++)
        if (g < cnt)
            m[g] = *(const float4*)(h + (size_t)p[g].x * 128 + lane * 4);

#pragma unroll
    for (int g = 0; g < GRP; g++)
        if (g < cnt) {
            float nm = __int_as_float(p[g].z);
            m[g].x *= nm; m[g].y *= nm; m[g].z *= nm; m[g].w *= nm;
        }

    float4 acc = m[0];
    int d = p[0].y;
#pragma unroll
    for (int g = 1; g < GRP; g++) {
        if (g < cnt) {
            if (p[g].y == d) {                 // warp-uniform branch
                acc.x += m[g].x; acc.y += m[g].y;
                acc.z += m[g].z; acc.w += m[g].w;
            } else {
                red4(agg + (size_t)d * 128 + lane * 4, acc.x, acc.y, acc.z, acc.w);
                acc = m[g];
                d = p[g].y;
            }
        }
    }
    red4(agg + (size_t)d * 128 + lane * 4, acc.x, acc.y, acc.z, acc.w);
}

// ---------------------------------------------------------------------------
// Layer-3 GEMM: relu(A)[n,128] @ [128,40] -> H3 and Out init (round-1 proven)
// ---------------------------------------------------------------------------
__global__ void __launch_bounds__(128)
gemm40_kernel(const float* __restrict__ A,
              const float* __restrict__ W,
              const float* __restrict__ bias,
              const float* __restrict__ dinv,
              float* __restrict__ Hout,
              float* __restrict__ Out,
              int n) {
    extern __shared__ float sm[];
    float* xs = sm;                 // 64 rows, stride 129
    float* ws = sm + 64 * 129;      // 128*40 flat

    const int tid = threadIdx.x;
    const int rb = blockIdx.x * 64;

    for (int l = tid * 4; l < 128 * 40; l += 128 * 4)
        *(float4*)(ws + l) = *(const float4*)(W + l);

    for (int f = tid; f < 2048; f += 128) {
        int row = f >> 5;
        int c = (f & 31) * 4;
        float4 v = make_float4(0.f, 0.f, 0.f, 0.f);
        int gr = rb + row;
        if (gr < n) v = *(const float4*)(A + (size_t)gr * 128 + c);
        float* xr = xs + row * 129 + c;
        xr[0] = fmaxf(v.x, 0.f);
        xr[1] = fmaxf(v.y, 0.f);
        xr[2] = fmaxf(v.z, 0.f);
        xr[3] = fmaxf(v.w, 0.f);
    }
    __syncthreads();

    const int tc = tid & 7;
    const int tr = tid >> 3;
    float acc[4][5];
#pragma unroll
    for (int r = 0; r < 4; r++)
#pragma unroll
        for (int j = 0; j < 5; j++) acc[r][j] = 0.0f;

#pragma unroll 4
    for (int k = 0; k < 128; k++) {
        float w[5];
#pragma unroll
        for (int j = 0; j < 5; j++) w[j] = ws[k * 40 + tc + 8 * j];
#pragma unroll
        for (int r = 0; r < 4; r++) {
            float a = xs[(tr * 4 + r) * 129 + k];
#pragma unroll
            for (int j = 0; j < 5; j++) acc[r][j] = fmaf(a, w[j], acc[r][j]);
        }
    }

#pragma unroll
    for (int r = 0; r < 4; r++) {
        int row = rb + tr * 4 + r;
        if (row >= n) break;
        float sl = dinv[row];
        sl = sl * sl;
#pragma unroll
        for (int j = 0; j < 5; j++) {
            int c = tc + 8 * j;
            float v = acc[r][j];
            Hout[(size_t)row * 40 + c] = v;
            Out[(size_t)row * 40 + c] = fmaf(v, sl, bias[c]);
        }
    }
}

// ---------------------------------------------------------------------------
// Segment-combining scatter (40 feats): lanes 0..9 carry the row.
// ---------------------------------------------------------------------------
__global__ void __launch_bounds__(256)
scatter40_grp(const float* __restrict__ h,
              const int4* __restrict__ pack,
              float* __restrict__ out, int e) {
    int w = (blockIdx.x * blockDim.x + threadIdx.x) >> 5;
    int lane = threadIdx.x & 31;
    int base = w * GRP;
    if (base >= e) return;
    int cnt = min(GRP, e - base);
    bool act = (lane < 10);

    int4 p[GRP];
#pragma unroll
    for (int g = 0; g < GRP; g++)
        if (g < cnt) p[g] = pack[base + g];

    float4 m[GRP];
#pragma unroll
    for (int g = 0; g < GRP; g++) {
        m[g] = make_float4(0.f, 0.f, 0.f, 0.f);
        if (g < cnt && act)
            m[g] = *(const float4*)(h + (size_t)p[g].x * 40 + lane * 4);
    }

#pragma unroll
    for (int g = 0; g < GRP; g++)
        if (g < cnt) {
            float nm = __int_as_float(p[g].z);
            m[g].x *= nm; m[g].y *= nm; m[g].z *= nm; m[g].w *= nm;
        }

    float4 acc = m[0];
    int d = p[0].y;
#pragma unroll
    for (int g = 1; g < GRP; g++) {
        if (g < cnt) {
            if (p[g].y == d) {
                acc.x += m[g].x; acc.y += m[g].y;
                acc.z += m[g].z; acc.w += m[g].w;
            } else {
                if (act)
                    red4(out + (size_t)d * 40 + lane * 4, acc.x, acc.y, acc.z, acc.w);
                acc = m[g];
                d = p[g].y;
            }
        }
    }
    if (act)
        red4(out + (size_t)d * 40 + lane * 4, acc.x, acc.y, acc.z, acc.w);
}

// ---------------------------------------------------------------------------
// Launch
// ---------------------------------------------------------------------------
extern "C" void kernel_launch(void* const* d_in, const int* in_sizes, int n_in,
                              void* d_out, int out_size) {
    const float* x  = (const float*)d_in[0];
    const int*   ei = (const int*)d_in[1];
    const float* ew = (const float*)d_in[2];
    const float* W1 = (const float*)d_in[3];
    const float* b1 = (const float*)d_in[4];
    const float* W2 = (const float*)d_in[5];
    const float* b2 = (const float*)d_in[6];
    const float* W3 = (const float*)d_in[7];
    const float* b3 = (const float*)d_in[8];
    float* out = (float*)d_out;

    const int n = in_sizes[0] / 128;       // 50000
    const int e = in_sizes[2];             // 640000
    const int* src = ei;
    const int* dst = ei + e;

    int *count, *offsets, *cursor;
    int4* pack;
    float *dinv, *h, *agg, *h3;
    cudaGetSymbolAddress((void**)&count,   g_count);
    cudaGetSymbolAddress((void**)&dinv,    g_dinv);
    cudaGetSymbolAddress((void**)&offsets, g_offsets);
    cudaGetSymbolAddress((void**)&cursor,  g_cursor);
    cudaGetSymbolAddress((void**)&pack,    g_pack);
    cudaGetSymbolAddress((void**)&h,       g_h);
    cudaGetSymbolAddress((void**)&agg,     g_agg);
    cudaGetSymbolAddress((void**)&h3,      g_h3);

    const int nb_n = (n + 255) / 256;
    const int nb_e = (e + 255) / 256;

    // Preamble: dst-sorted edge pack + dinv
    zero_kernel<<<nb_n, 256>>>(count, dinv, n);
    hist_kernel<<<nb_e, 256>>>(dst, ew, count, dinv, e);
    scan_kernel<<<1, 1024>>>(count, dinv, offsets, cursor, n);
    fill_kernel<<<nb_e, 256>>>(src, dst, ew, dinv, cursor, pack, e);

    const int gemm_blocks = (n + 127) / 128;
    const int groups = (e + GRP - 1) / GRP;
    const int scat_blocks = (groups * 32 + 255) / 256;

    // Layer 1
    gemm128_kernel<false><<<gemm_blocks, 256>>>(x, W1, b1, dinv, h, agg, n);
    scatter128_grp<<<scat_blocks, 256>>>(h, pack, agg, e);

    // Layer 2 (relu fused into GEMM A-load; in-place agg safe: block-local rows)
    gemm128_kernel<true><<<gemm_blocks, 256>>>(agg, W2, b2, dinv, h, agg, n);
    scatter128_grp<<<scat_blocks, 256>>>(h, pack, agg, e);

    // Layer 3 (relu fused; scatter straight to d_out)
    static const int g40_smem = (64 * 129 + 128 * 40) * sizeof(float);
    cudaFuncSetAttribute(gemm40_kernel,
                         cudaFuncAttributeMaxDynamicSharedMemorySize, g40_smem);
    gemm40_kernel<<<(n + 63) / 64, 128, g40_smem>>>(agg, W3, b3, dinv, h3, out, n);
    scatter40_grp<<<scat_blocks, 256>>>(h3, pack, out, e);
}

// round 8
// speedup vs baseline: 1.1296x; 1.0180x over previous
#include <cuda_runtime.h>

// Problem constants (fixed by the dataset)
#define NMAX 50000
#define EMAX 640000
#define GRP 8
#define PERM 1000003LL   // prime > max group count -> always coprime

// Scratch (allocation-free rule: __device__ globals)
__device__ int   g_count[NMAX];         // in-degree counts (by dst)
__device__ float g_dinv[NMAX];          // weighted in-degree (incl self) -> rsqrt
__device__ int   g_offsets[NMAX + 1];   // sorted-edge row offsets (by dst)
__device__ int   g_cursor[NMAX];        // fill cursors
__device__ int4  g_pack[EMAX];          // {src, dst, norm_bits, 0}, sorted by dst
__device__ float g_h[NMAX * 128];       // GEMM output (pre-aggregation)
__device__ float g_agg1[NMAX * 128];    // layer-1 aggregation
__device__ float g_agg2[NMAX * 128];    // layer-2 aggregation
__device__ float g_h3[NMAX * 40];       // layer-3 GEMM output

__device__ __forceinline__ void red4(float* p, float a, float b, float c, float d) {
    asm volatile("red.global.add.v4.f32 [%0], {%1, %2, %3, %4};"
                 :: "l"(p), "f"(a), "f"(b), "f"(c), "f"(d) : "memory");
}

// ---------------------------------------------------------------------------
// Preamble: histogram + weighted degree (both by dst)
// ---------------------------------------------------------------------------
__global__ void zero_kernel(int* count, float* deg, int n) {
    int i = blockIdx.x * blockDim.x + threadIdx.x;
    if (i < n) { count[i] = 0; deg[i] = 1.0f; }  // self-loop weight
}

__global__ void hist_kernel(const int* __restrict__ dst,
                            const float* __restrict__ ew,
                            int* __restrict__ count,
                            float* __restrict__ deg, int e) {
    int i = blockIdx.x * blockDim.x + threadIdx.x;
    if (i < e) {
        int d = dst[i];
        atomicAdd(count + d, 1);
        atomicAdd(deg + d, ew[i]);
    }
}

// Single-block exclusive scan of count[n] -> offsets/cursor; deg -> rsqrt(deg).
__global__ void __launch_bounds__(1024)
scan_kernel(const int* __restrict__ count,
            float* __restrict__ deg_dinv,
            int* __restrict__ offsets,
            int* __restrict__ cursor, int n) {
    __shared__ int part[1024];
    const int t = threadIdx.x;
    const int C = (n + 1023) / 1024;
    const int base = t * C;

    int sum = 0;
    for (int i = 0; i < C; i++) {
        int idx = base + i;
        sum += (idx < n) ? count[idx] : 0;
    }
    part[t] = sum;
    __syncthreads();
    for (int off = 1; off < 1024; off <<= 1) {
        int v = (t >= off) ? part[t - off] : 0;
        __syncthreads();
        part[t] += v;
        __syncthreads();
    }
    int run = (t > 0) ? part[t - 1] : 0;
    for (int i = 0; i < C; i++) {
        int idx = base + i;
        if (idx < n) {
            offsets[idx] = run;
            cursor[idx] = run;
            run += count[idx];
        }
    }
    if (t == 1023) offsets[n] = part[1023];

    for (int i = t; i < n; i += 1024) deg_dinv[i] = rsqrtf(deg_dinv[i]);
}

// Sort-by-dst fill; norm computed here.
__global__ void fill_kernel(const int* __restrict__ src,
                            const int* __restrict__ dst,
                            const float* __restrict__ ew,
                            const float* __restrict__ dinv,
                            int* __restrict__ cursor,
                            int4* __restrict__ pack, int e) {
    int i = blockIdx.x * blockDim.x + threadIdx.x;
    if (i >= e) return;
    int s = src[i];
    int d = dst[i];
    int pos = atomicAdd(cursor + d, 1);
    int4 p;
    p.x = s;
    p.y = d;
    p.z = __float_as_int(dinv[s] * ew[i] * dinv[d]);
    p.w = 0;
    pack[pos] = p;
}

// agg = h*dinv^2 + bias  (layer-1 epilogue, decoupled so gemm1 can overlap preamble)
__global__ void agg_init128(const float* __restrict__ h,
                            const float* __restrict__ dinv,
                            const float* __restrict__ bias,
                            float* __restrict__ agg, int n) {
    int idx = blockIdx.x * blockDim.x + threadIdx.x;   // float4 index
    if (idx >= n * 32) return;
    int row = idx >> 5;
    int c = idx & 31;
    float di = dinv[row];
    di *= di;
    float4 hv = ((const float4*)h)[idx];
    float4 bv = ((const float4*)bias)[c];
    ((float4*)agg)[idx] = make_float4(fmaf(hv.x, di, bv.x), fmaf(hv.y, di, bv.y),
                                      fmaf(hv.z, di, bv.z), fmaf(hv.w, di, bv.w));
}

// ---------------------------------------------------------------------------
// GEMM: [n,128] @ [128,128]. FUSE_EPI: also write Agg = H*dinv^2 + bias.
// (round-1 proven kernel)
// ---------------------------------------------------------------------------
template <bool RELU_IN, bool FUSE_EPI>
__global__ void __launch_bounds__(256, 2)
gemm128_kernel(const float* __restrict__ A,
               const float* __restrict__ W,
               const float* __restrict__ bias,
               const float* __restrict__ dinv,
               float* __restrict__ Hout,
               float* __restrict__ AggOut,
               int n) {
    __shared__ float As[16][128];  // As[k][m]
    __shared__ float Bs[16][128];  // Bs[k][n]

    const int tid = threadIdx.x;
    const int tx = tid & 15;
    const int ty = tid >> 4;
    const int rb = blockIdx.x * 128;

    float acc[8][8];
#pragma unroll
    for (int i = 0; i < 8; i++)
#pragma unroll
        for (int j = 0; j < 8; j++) acc[i][j] = 0.0f;

    for (int k0 = 0; k0 < 128; k0 += 16) {
#pragma unroll
        for (int l = 0; l < 2; l++) {
            int f = tid + l * 256;
            int row = f >> 2;
            int c4 = (f & 3) * 4;
            float4 v = make_float4(0.f, 0.f, 0.f, 0.f);
            int gr = rb + row;
            if (gr < n) v = *(const float4*)(A + (size_t)gr * 128 + k0 + c4);
            if (RELU_IN) {
                v.x = fmaxf(v.x, 0.f); v.y = fmaxf(v.y, 0.f);
                v.z = fmaxf(v.z, 0.f); v.w = fmaxf(v.w, 0.f);
            }
            As[c4 + 0][row] = v.x;
            As[c4 + 1][row] = v.y;
            As[c4 + 2][row] = v.z;
            As[c4 + 3][row] = v.w;
        }
#pragma unroll
        for (int l = 0; l < 2; l++) {
            int f = tid + l * 256;
            int kr = f >> 5;
            int c = (f & 31) * 4;
            *(float4*)&Bs[kr][c] = *(const float4*)(W + (size_t)(k0 + kr) * 128 + c);
        }
        __syncthreads();

#pragma unroll
        for (int k = 0; k < 16; k++) {
            float4 a0 = *(const float4*)&As[k][ty * 8];
            float4 a1 = *(const float4*)&As[k][ty * 8 + 4];
            float4 b0 = *(const float4*)&Bs[k][tx * 8];
            float4 b1 = *(const float4*)&Bs[k][tx * 8 + 4];
            float a[8] = {a0.x, a0.y, a0.z, a0.w, a1.x, a1.y, a1.z, a1.w};
            float b[8] = {b0.x, b0.y, b0.z, b0.w, b1.x, b1.y, b1.z, b1.w};
#pragma unroll
            for (int i = 0; i < 8; i++)
#pragma unroll
                for (int j = 0; j < 8; j++)
                    acc[i][j] = fmaf(a[i], b[j], acc[i][j]);
        }
        __syncthreads();
    }

#pragma unroll
    for (int i = 0; i < 8; i++) {
        int row = rb + ty * 8 + i;
        if (row >= n) break;
        float sl = 0.f;
        if (FUSE_EPI) { sl = dinv[row]; sl *= sl; }
#pragma unroll
        for (int j = 0; j < 8; j += 4) {
            int col = tx * 8 + j;
            float4 hv = make_float4(acc[i][j], acc[i][j + 1], acc[i][j + 2], acc[i][j + 3]);
            *(float4*)(Hout + (size_t)row * 128 + col) = hv;
            if (FUSE_EPI) {
                float4 bv = *(const float4*)(bias + col);
                float4 av;
                av.x = fmaf(hv.x, sl, bv.x);
                av.y = fmaf(hv.y, sl, bv.y);
                av.z = fmaf(hv.z, sl, bv.z);
                av.w = fmaf(hv.w, sl, bv.w);
                *(float4*)(AggOut + (size_t)row * 128 + col) = av;
            }
        }
    }
}

// ---------------------------------------------------------------------------
// Permuted segment-combining scatter (128 feats): one warp per GRP dst-sorted
// edges, group order permuted so concurrent warps red to DISTINCT dsts.
// ---------------------------------------------------------------------------
__global__ void __launch_bounds__(256)
scatter128_perm(const float* __restrict__ h,
                const int4* __restrict__ pack,
                float* __restrict__ agg, int e, int nw) {
    int w = (blockIdx.x * blockDim.x + threadIdx.x) >> 5;
    int lane = threadIdx.x & 31;
    if (w >= nw) return;
    w = (int)(((long long)w * PERM) % nw);   // decorrelate concurrent dsts
    int base = w * GRP;
    int cnt = min(GRP, e - base);

    int4 p[GRP];
#pragma unroll
    for (int g = 0; g < GRP; g++)
        if (g < cnt) p[g] = pack[base + g];

    float4 m[GRP];
#pragma unroll
    for (int g = 0; g < GRP; g++)
        if (g < cnt)
            m[g] = *(const float4*)(h + (size_t)p[g].x * 128 + lane * 4);

#pragma unroll
    for (int g = 0; g < GRP; g++)
        if (g < cnt) {
            float nm = __int_as_float(p[g].z);
            m[g].x *= nm; m[g].y *= nm; m[g].z *= nm; m[g].w *= nm;
        }

    float4 acc = m[0];
    int d = p[0].y;
#pragma unroll
    for (int g = 1; g < GRP; g++) {
        if (g < cnt) {
            if (p[g].y == d) {                 // warp-uniform branch
                acc.x += m[g].x; acc.y += m[g].y;
                acc.z += m[g].z; acc.w += m[g].w;
            } else {
                red4(agg + (size_t)d * 128 + lane * 4, acc.x, acc.y, acc.z, acc.w);
                acc = m[g];
                d = p[g].y;
            }
        }
    }
    red4(agg + (size_t)d * 128 + lane * 4, acc.x, acc.y, acc.z, acc.w);
}

// ---------------------------------------------------------------------------
// Layer-3 GEMM: relu(A)[n,128] @ [128,40] -> H3 and Out init (round-1 proven)
// ---------------------------------------------------------------------------
__global__ void __launch_bounds__(128)
gemm40_kernel(const float* __restrict__ A,
              const float* __restrict__ W,
              const float* __restrict__ bias,
              const float* __restrict__ dinv,
              float* __restrict__ Hout,
              float* __restrict__ Out,
              int n) {
    extern __shared__ float sm[];
    float* xs = sm;                 // 64 rows, stride 129
    float* ws = sm + 64 * 129;      // 128*40 flat

    const int tid = threadIdx.x;
    const int rb = blockIdx.x * 64;

    for (int l = tid * 4; l < 128 * 40; l += 128 * 4)
        *(float4*)(ws + l) = *(const float4*)(W + l);

    for (int f = tid; f < 2048; f += 128) {
        int row = f >> 5;
        int c = (f & 31) * 4;
        float4 v = make_float4(0.f, 0.f, 0.f, 0.f);
        int gr = rb + row;
        if (gr < n) v = *(const float4*)(A + (size_t)gr * 128 + c);
        float* xr = xs + row * 129 + c;
        xr[0] = fmaxf(v.x, 0.f);
        xr[1] = fmaxf(v.y, 0.f);
        xr[2] = fmaxf(v.z, 0.f);
        xr[3] = fmaxf(v.w, 0.f);
    }
    __syncthreads();

    const int tc = tid & 7;
    const int tr = tid >> 3;
    float acc[4][5];
#pragma unroll
    for (int r = 0; r < 4; r++)
#pragma unroll
        for (int j = 0; j < 5; j++) acc[r][j] = 0.0f;

#pragma unroll 4
    for (int k = 0; k < 128; k++) {
        float w[5];
#pragma unroll
        for (int j = 0; j < 5; j++) w[j] = ws[k * 40 + tc + 8 * j];
#pragma unroll
        for (int r = 0; r < 4; r++) {
            float a = xs[(tr * 4 + r) * 129 + k];
#pragma unroll
            for (int j = 0; j < 5; j++) acc[r][j] = fmaf(a, w[j], acc[r][j]);
        }
    }

#pragma unroll
    for (int r = 0; r < 4; r++) {
        int row = rb + tr * 4 + r;
        if (row >= n) break;
        float sl = dinv[row];
        sl = sl * sl;
#pragma unroll
        for (int j = 0; j < 5; j++) {
            int c = tc + 8 * j;
            float v = acc[r][j];
            Hout[(size_t)row * 40 + c] = v;
            Out[(size_t)row * 40 + c] = fmaf(v, sl, bias[c]);
        }
    }
}

// ---------------------------------------------------------------------------
// Permuted segment-combining scatter (40 feats): lanes 0..9 carry the row.
// ---------------------------------------------------------------------------
__global__ void __launch_bounds__(256)
scatter40_perm(const float* __restrict__ h,
               const int4* __restrict__ pack,
               float* __restrict__ out, int e, int nw) {
    int w = (blockIdx.x * blockDim.x + threadIdx.x) >> 5;
    int lane = threadIdx.x & 31;
    if (w >= nw) return;
    w = (int)(((long long)w * PERM) % nw);
    int base = w * GRP;
    int cnt = min(GRP, e - base);
    bool act = (lane < 10);

    int4 p[GRP];
#pragma unroll
    for (int g = 0; g < GRP; g++)
        if (g < cnt) p[g] = pack[base + g];

    float4 m[GRP];
#pragma unroll
    for (int g = 0; g < GRP; g++) {
        m[g] = make_float4(0.f, 0.f, 0.f, 0.f);
        if (g < cnt && act)
            m[g] = *(const float4*)(h + (size_t)p[g].x * 40 + lane * 4);
    }

#pragma unroll
    for (int g = 0; g < GRP; g++)
        if (g < cnt) {
            float nm = __int_as_float(p[g].z);
            m[g].x *= nm; m[g].y *= nm; m[g].z *= nm; m[g].w *= nm;
        }

    float4 acc = m[0];
    int d = p[0].y;
#pragma unroll
    for (int g = 1; g < GRP; g++) {
        if (g < cnt) {
            if (p[g].y == d) {
                acc.x += m[g].x; acc.y += m[g].y;
                acc.z += m[g].z; acc.w += m[g].w;
            } else {
                if (act)
                    red4(out + (size_t)d * 40 + lane * 4, acc.x, acc.y, acc.z, acc.w);
                acc = m[g];
                d = p[g].y;
            }
        }
    }
    if (act)
        red4(out + (size_t)d * 40 + lane * 4, acc.x, acc.y, acc.z, acc.w);
}

// ---------------------------------------------------------------------------
// Launch: gemm1 overlaps the graph preamble on a second stream.
// ---------------------------------------------------------------------------
extern "C" void kernel_launch(void* const* d_in, const int* in_sizes, int n_in,
                              void* d_out, int out_size) {
    const float* x  = (const float*)d_in[0];
    const int*   ei = (const int*)d_in[1];
    const float* ew = (const float*)d_in[2];
    const float* W1 = (const float*)d_in[3];
    const float* b1 = (const float*)d_in[4];
    const float* W2 = (const float*)d_in[5];
    const float* b2 = (const float*)d_in[6];
    const float* W3 = (const float*)d_in[7];
    const float* b3 = (const float*)d_in[8];
    float* out = (float*)d_out;

    const int n = in_sizes[0] / 128;       // 50000
    const int e = in_sizes[2];             // 640000
    const int* src = ei;
    const int* dst = ei + e;

    int *count, *offsets, *cursor;
    int4* pack;
    float *dinv, *h, *agg1, *agg2, *h3;
    cudaGetSymbolAddress((void**)&count,   g_count);
    cudaGetSymbolAddress((void**)&dinv,    g_dinv);
    cudaGetSymbolAddress((void**)&offsets, g_offsets);
    cudaGetSymbolAddress((void**)&cursor,  g_cursor);
    cudaGetSymbolAddress((void**)&pack,    g_pack);
    cudaGetSymbolAddress((void**)&h,       g_h);
    cudaGetSymbolAddress((void**)&agg1,    g_agg1);
    cudaGetSymbolAddress((void**)&agg2,    g_agg2);
    cudaGetSymbolAddress((void**)&h3,      g_h3);

    static cudaStream_t s2 = nullptr;
    static cudaEvent_t evFork = nullptr, evG1 = nullptr;
    if (s2 == nullptr) {
        cudaStreamCreateWithFlags(&s2, cudaStreamNonBlocking);
        cudaEventCreateWithFlags(&evFork, cudaEventDisableTiming);
        cudaEventCreateWithFlags(&evG1, cudaEventDisableTiming);
    }

    const int nb_n = (n + 255) / 256;
    const int nb_e = (e + 255) / 256;
    const int gemm_blocks = (n + 127) / 128;
    const int nw = (e + GRP - 1) / GRP;
    const int scat_blocks = (nw * 32 + 255) / 256;

    // Fork: gemm1 (graph-independent, H only) on s2
    cudaEventRecord(evFork, 0);
    cudaStreamWaitEvent(s2, evFork, 0);
    gemm128_kernel<false, false><<<gemm_blocks, 256, 0, s2>>>(
        x, W1, nullptr, nullptr, h, nullptr, n);
    cudaEventRecord(evG1, s2);

    // Preamble on main stream (concurrent with gemm1)
    zero_kernel<<<nb_n, 256>>>(count, dinv, n);
    hist_kernel<<<nb_e, 256>>>(dst, ew, count, dinv, e);
    scan_kernel<<<1, 1024>>>(count, dinv, offsets, cursor, n);
    fill_kernel<<<nb_e, 256>>>(src, dst, ew, dinv, cursor, pack, e);

    // Join, then layer-1 epilogue + scatter
    cudaStreamWaitEvent(0, evG1, 0);
    agg_init128<<<(n * 32 + 255) / 256, 256>>>(h, dinv, b1, agg1, n);
    scatter128_perm<<<scat_blocks, 256>>>(h, pack, agg1, e, nw);

    // Layer 2 (relu + fused epilogue)
    gemm128_kernel<true, true><<<gemm_blocks, 256>>>(agg1, W2, b2, dinv, h, agg2, n);
    scatter128_perm<<<scat_blocks, 256>>>(h, pack, agg2, e, nw);

    // Layer 3 (relu fused; scatter straight to d_out)
    static const int g40_smem = (64 * 129 + 128 * 40) * sizeof(float);
    cudaFuncSetAttribute(gemm40_kernel,
                         cudaFuncAttributeMaxDynamicSharedMemorySize, g40_smem);
    gemm40_kernel<<<(n + 63) / 64, 128, g40_smem>>>(agg2, W3, b3, dinv, h3, out, n);
    scatter40_perm<<<scat_blocks, 256>>>(h3, pack, out, e, nw);
}

// round 9
// speedup vs baseline: 1.3885x; 1.2292x over previous
#include <cuda_runtime.h>

// Problem constants (fixed by the dataset)
#define NMAX 50000
#define EMAX 640000
#define GRP 8
#define PERM 1000003LL   // prime > max group count -> always coprime
#define SCAN_CHUNK 1024  // elements per scan block

// Scratch (allocation-free rule: __device__ globals)
__device__ int   g_count[NMAX];         // in-degree counts (by dst)
__device__ float g_dinv[NMAX];          // weighted in-degree (incl self) -> rsqrt
__device__ int   g_part[256];           // scan partials
__device__ int   g_cursor[NMAX];        // fill cursors (exclusive scan of count)
__device__ int4  g_pack[EMAX];          // {src, dst, norm_bits, 0}, sorted by dst
__device__ float g_h[NMAX * 128];       // GEMM output (pre-aggregation)
__device__ float g_agg1[NMAX * 128];    // layer-1 aggregation
__device__ float g_agg2[NMAX * 128];    // layer-2 aggregation
__device__ float g_h3[NMAX * 40];       // layer-3 GEMM output

__device__ __forceinline__ void red4(float* p, float a, float b, float c, float d) {
    asm volatile("red.global.add.v4.f32 [%0], {%1, %2, %3, %4};"
                 :: "l"(p), "f"(a), "f"(b), "f"(c), "f"(d) : "memory");
}

// ---------------------------------------------------------------------------
// Preamble: histogram + weighted degree (both by dst)
// ---------------------------------------------------------------------------
__global__ void zero_kernel(int* count, float* deg, int n) {
    int i = blockIdx.x * blockDim.x + threadIdx.x;
    if (i < n) { count[i] = 0; deg[i] = 1.0f; }  // self-loop weight
}

__global__ void hist_kernel(const int* __restrict__ dst,
                            const float* __restrict__ ew,
                            int* __restrict__ count,
                            float* __restrict__ deg, int e) {
    int i = blockIdx.x * blockDim.x + threadIdx.x;
    if (i < e) {
        int d = dst[i];
        atomicAdd(count + d, 1);
        atomicAdd(deg + d, ew[i]);
    }
}

// ---- parallel exclusive scan of count[n] (3 kernels) ----
// 1) per-block partial sums (block = SCAN_CHUNK elements, 256 threads x 4)
__global__ void __launch_bounds__(256)
partial_kernel(const int* __restrict__ count, int* __restrict__ part, int n) {
    const int t = threadIdx.x;
    const int base = blockIdx.x * SCAN_CHUNK + t * 4;
    int s = 0;
#pragma unroll
    for (int i = 0; i < 4; i++) {
        int idx = base + i;
        if (idx < n) s += count[idx];
    }
#pragma unroll
    for (int o = 16; o; o >>= 1) s += __shfl_down_sync(~0u, s, o);
    __shared__ int wsum[8];
    if ((t & 31) == 0) wsum[t >> 5] = s;
    __syncthreads();
    if (t == 0) {
        int v = 0;
#pragma unroll
        for (int i = 0; i < 8; i++) v += wsum[i];
        part[blockIdx.x] = v;
    }
}

// 2) single-block exclusive scan of the (<=256) partials
__global__ void __launch_bounds__(256)
scanpart_kernel(int* __restrict__ part, int nb) {
    __shared__ int sh[256];
    const int t = threadIdx.x;
    int orig = (t < nb) ? part[t] : 0;
    sh[t] = orig;
    __syncthreads();
    for (int off = 1; off < 256; off <<= 1) {
        int v = (t >= off) ? sh[t - off] : 0;
        __syncthreads();
        sh[t] += v;
        __syncthreads();
    }
    if (t < nb) part[t] = sh[t] - orig;   // exclusive
}

// 3) final: block-local exclusive scan + partial offset -> cursor; also dinv.
__global__ void __launch_bounds__(256)
scanfinal_kernel(const int* __restrict__ count,
                 const int* __restrict__ part,
                 float* __restrict__ deg_dinv,
                 int* __restrict__ cursor, int n) {
    const int t = threadIdx.x;
    const int base = blockIdx.x * SCAN_CHUNK + t * 4;
    int c[4];
    int s = 0;
#pragma unroll
    for (int i = 0; i < 4; i++) {
        int idx = base + i;
        c[i] = (idx < n) ? count[idx] : 0;
        s += c[i];
    }
    // warp-inclusive scan of thread sums
    int inc = s;
#pragma unroll
    for (int o = 1; o < 32; o <<= 1) {
        int v = __shfl_up_sync(~0u, inc, o);
        if ((t & 31) >= o) inc += v;
    }
    __shared__ int wtot[8], woff[8];
    if ((t & 31) == 31) wtot[t >> 5] = inc;
    __syncthreads();
    if (t == 0) {
        int run = 0;
#pragma unroll
        for (int i = 0; i < 8; i++) { woff[i] = run; run += wtot[i]; }
    }
    __syncthreads();
    int run = inc - s + woff[t >> 5] + part[blockIdx.x];
#pragma unroll
    for (int i = 0; i < 4; i++) {
        int idx = base + i;
        if (idx < n) {
            cursor[idx] = run;
            run += c[i];
            deg_dinv[idx] = rsqrtf(deg_dinv[idx]);
        }
    }
}

// Sort-by-dst fill; norm computed here.
__global__ void fill_kernel(const int* __restrict__ src,
                            const int* __restrict__ dst,
                            const float* __restrict__ ew,
                            const float* __restrict__ dinv,
                            int* __restrict__ cursor,
                            int4* __restrict__ pack, int e) {
    int i = blockIdx.x * blockDim.x + threadIdx.x;
    if (i >= e) return;
    int s = src[i];
    int d = dst[i];
    int pos = atomicAdd(cursor + d, 1);
    int4 p;
    p.x = s;
    p.y = d;
    p.z = __float_as_int(dinv[s] * ew[i] * dinv[d]);
    p.w = 0;
    pack[pos] = p;
}

// agg = h*dinv^2 + bias  (layer-1 epilogue, decoupled so gemm1 overlaps preamble)
__global__ void agg_init128(const float* __restrict__ h,
                            const float* __restrict__ dinv,
                            const float* __restrict__ bias,
                            float* __restrict__ agg, int n) {
    int idx = blockIdx.x * blockDim.x + threadIdx.x;   // float4 index
    if (idx >= n * 32) return;
    int row = idx >> 5;
    int c = idx & 31;
    float di = dinv[row];
    di *= di;
    float4 hv = ((const float4*)h)[idx];
    float4 bv = ((const float4*)bias)[c];
    ((float4*)agg)[idx] = make_float4(fmaf(hv.x, di, bv.x), fmaf(hv.y, di, bv.y),
                                      fmaf(hv.z, di, bv.z), fmaf(hv.w, di, bv.w));
}

// ---------------------------------------------------------------------------
// GEMM: [n,128] @ [128,128]. FUSE_EPI: also write Agg = H*dinv^2 + bias.
// ---------------------------------------------------------------------------
template <bool RELU_IN, bool FUSE_EPI>
__global__ void __launch_bounds__(256, 2)
gemm128_kernel(const float* __restrict__ A,
               const float* __restrict__ W,
               const float* __restrict__ bias,
               const float* __restrict__ dinv,
               float* __restrict__ Hout,
               float* __restrict__ AggOut,
               int n) {
    __shared__ float As[16][128];  // As[k][m]
    __shared__ float Bs[16][128];  // Bs[k][n]

    const int tid = threadIdx.x;
    const int tx = tid & 15;
    const int ty = tid >> 4;
    const int rb = blockIdx.x * 128;

    float acc[8][8];
#pragma unroll
    for (int i = 0; i < 8; i++)
#pragma unroll
        for (int j = 0; j < 8; j++) acc[i][j] = 0.0f;

    for (int k0 = 0; k0 < 128; k0 += 16) {
#pragma unroll
        for (int l = 0; l < 2; l++) {
            int f = tid + l * 256;
            int row = f >> 2;
            int c4 = (f & 3) * 4;
            float4 v = make_float4(0.f, 0.f, 0.f, 0.f);
            int gr = rb + row;
            if (gr < n) v = *(const float4*)(A + (size_t)gr * 128 + k0 + c4);
            if (RELU_IN) {
                v.x = fmaxf(v.x, 0.f); v.y = fmaxf(v.y, 0.f);
                v.z = fmaxf(v.z, 0.f); v.w = fmaxf(v.w, 0.f);
            }
            As[c4 + 0][row] = v.x;
            As[c4 + 1][row] = v.y;
            As[c4 + 2][row] = v.z;
            As[c4 + 3][row] = v.w;
        }
#pragma unroll
        for (int l = 0; l < 2; l++) {
            int f = tid + l * 256;
            int kr = f >> 5;
            int c = (f & 31) * 4;
            *(float4*)&Bs[kr][c] = *(const float4*)(W + (size_t)(k0 + kr) * 128 + c);
        }
        __syncthreads();

#pragma unroll
        for (int k = 0; k < 16; k++) {
            float4 a0 = *(const float4*)&As[k][ty * 8];
            float4 a1 = *(const float4*)&As[k][ty * 8 + 4];
            float4 b0 = *(const float4*)&Bs[k][tx * 8];
            float4 b1 = *(const float4*)&Bs[k][tx * 8 + 4];
            float a[8] = {a0.x, a0.y, a0.z, a0.w, a1.x, a1.y, a1.z, a1.w};
            float b[8] = {b0.x, b0.y, b0.z, b0.w, b1.x, b1.y, b1.z, b1.w};
#pragma unroll
            for (int i = 0; i < 8; i++)
#pragma unroll
                for (int j = 0; j < 8; j++)
                    acc[i][j] = fmaf(a[i], b[j], acc[i][j]);
        }
        __syncthreads();
    }

#pragma unroll
    for (int i = 0; i < 8; i++) {
        int row = rb + ty * 8 + i;
        if (row >= n) break;
        float sl = 0.f;
        if (FUSE_EPI) { sl = dinv[row]; sl *= sl; }
#pragma unroll
        for (int j = 0; j < 8; j += 4) {
            int col = tx * 8 + j;
            float4 hv = make_float4(acc[i][j], acc[i][j + 1], acc[i][j + 2], acc[i][j + 3]);
            *(float4*)(Hout + (size_t)row * 128 + col) = hv;
            if (FUSE_EPI) {
                float4 bv = *(const float4*)(bias + col);
                float4 av;
                av.x = fmaf(hv.x, sl, bv.x);
                av.y = fmaf(hv.y, sl, bv.y);
                av.z = fmaf(hv.z, sl, bv.z);
                av.w = fmaf(hv.w, sl, bv.w);
                *(float4*)(AggOut + (size_t)row * 128 + col) = av;
            }
        }
    }
}

// ---------------------------------------------------------------------------
// Permuted segment-combining scatter (128 feats)
// ---------------------------------------------------------------------------
__global__ void __launch_bounds__(256)
scatter128_perm(const float* __restrict__ h,
                const int4* __restrict__ pack,
                float* __restrict__ agg, int e, int nw) {
    int w = (blockIdx.x * blockDim.x + threadIdx.x) >> 5;
    int lane = threadIdx.x & 31;
    if (w >= nw) return;
    w = (int)(((long long)w * PERM) % nw);   // decorrelate concurrent dsts
    int base = w * GRP;
    int cnt = min(GRP, e - base);

    int4 p[GRP];
#pragma unroll
    for (int g = 0; g < GRP; g++)
        if (g < cnt) p[g] = pack[base + g];

    float4 m[GRP];
#pragma unroll
    for (int g = 0; g < GRP; g++)
        if (g < cnt)
            m[g] = *(const float4*)(h + (size_t)p[g].x * 128 + lane * 4);

#pragma unroll
    for (int g = 0; g < GRP; g++)
        if (g < cnt) {
            float nm = __int_as_float(p[g].z);
            m[g].x *= nm; m[g].y *= nm; m[g].z *= nm; m[g].w *= nm;
        }

    float4 acc = m[0];
    int d = p[0].y;
#pragma unroll
    for (int g = 1; g < GRP; g++) {
        if (g < cnt) {
            if (p[g].y == d) {                 // warp-uniform branch
                acc.x += m[g].x; acc.y += m[g].y;
                acc.z += m[g].z; acc.w += m[g].w;
            } else {
                red4(agg + (size_t)d * 128 + lane * 4, acc.x, acc.y, acc.z, acc.w);
                acc = m[g];
                d = p[g].y;
            }
        }
    }
    red4(agg + (size_t)d * 128 + lane * 4, acc.x, acc.y, acc.z, acc.w);
}

// ---------------------------------------------------------------------------
// Layer-3 GEMM: relu(A)[n,128] @ [128,40] -> H3 and Out init
// ---------------------------------------------------------------------------
__global__ void __launch_bounds__(128)
gemm40_kernel(const float* __restrict__ A,
              const float* __restrict__ W,
              const float* __restrict__ bias,
              const float* __restrict__ dinv,
              float* __restrict__ Hout,
              float* __restrict__ Out,
              int n) {
    extern __shared__ float sm[];
    float* xs = sm;                 // 64 rows, stride 129
    float* ws = sm + 64 * 129;      // 128*40 flat

    const int tid = threadIdx.x;
    const int rb = blockIdx.x * 64;

    for (int l = tid * 4; l < 128 * 40; l += 128 * 4)
        *(float4*)(ws + l) = *(const float4*)(W + l);

    for (int f = tid; f < 2048; f += 128) {
        int row = f >> 5;
        int c = (f & 31) * 4;
        float4 v = make_float4(0.f, 0.f, 0.f, 0.f);
        int gr = rb + row;
        if (gr < n) v = *(const float4*)(A + (size_t)gr * 128 + c);
        float* xr = xs + row * 129 + c;
        xr[0] = fmaxf(v.x, 0.f);
        xr[1] = fmaxf(v.y, 0.f);
        xr[2] = fmaxf(v.z, 0.f);
        xr[3] = fmaxf(v.w, 0.f);
    }
    __syncthreads();

    const int tc = tid & 7;
    const int tr = tid >> 3;
    float acc[4][5];
#pragma unroll
    for (int r = 0; r < 4; r++)
#pragma unroll
        for (int j = 0; j < 5; j++) acc[r][j] = 0.0f;

#pragma unroll 4
    for (int k = 0; k < 128; k++) {
        float w[5];
#pragma unroll
        for (int j = 0; j < 5; j++) w[j] = ws[k * 40 + tc + 8 * j];
#pragma unroll
        for (int r = 0; r < 4; r++) {
            float a = xs[(tr * 4 + r) * 129 + k];
#pragma unroll
            for (int j = 0; j < 5; j++) acc[r][j] = fmaf(a, w[j], acc[r][j]);
        }
    }

#pragma unroll
    for (int r = 0; r < 4; r++) {
        int row = rb + tr * 4 + r;
        if (row >= n) break;
        float sl = dinv[row];
        sl = sl * sl;
#pragma unroll
        for (int j = 0; j < 5; j++) {
            int c = tc + 8 * j;
            float v = acc[r][j];
            Hout[(size_t)row * 40 + c] = v;
            Out[(size_t)row * 40 + c] = fmaf(v, sl, bias[c]);
        }
    }
}

// ---------------------------------------------------------------------------
// Permuted segment-combining scatter (40 feats): lanes 0..9 carry the row.
// ---------------------------------------------------------------------------
__global__ void __launch_bounds__(256)
scatter40_perm(const float* __restrict__ h,
               const int4* __restrict__ pack,
               float* __restrict__ out, int e, int nw) {
    int w = (blockIdx.x * blockDim.x + threadIdx.x) >> 5;
    int lane = threadIdx.x & 31;
    if (w >= nw) return;
    w = (int)(((long long)w * PERM) % nw);
    int base = w * GRP;
    int cnt = min(GRP, e - base);
    bool act = (lane < 10);

    int4 p[GRP];
#pragma unroll
    for (int g = 0; g < GRP; g++)
        if (g < cnt) p[g] = pack[base + g];

    float4 m[GRP];
#pragma unroll
    for (int g = 0; g < GRP; g++) {
        m[g] = make_float4(0.f, 0.f, 0.f, 0.f);
        if (g < cnt && act)
            m[g] = *(const float4*)(h + (size_t)p[g].x * 40 + lane * 4);
    }

#pragma unroll
    for (int g = 0; g < GRP; g++)
        if (g < cnt) {
            float nm = __int_as_float(p[g].z);
            m[g].x *= nm; m[g].y *= nm; m[g].z *= nm; m[g].w *= nm;
        }

    float4 acc = m[0];
    int d = p[0].y;
#pragma unroll
    for (int g = 1; g < GRP; g++) {
        if (g < cnt) {
            if (p[g].y == d) {
                acc.x += m[g].x; acc.y += m[g].y;
                acc.z += m[g].z; acc.w += m[g].w;
            } else {
                if (act)
                    red4(out + (size_t)d * 40 + lane * 4, acc.x, acc.y, acc.z, acc.w);
                acc = m[g];
                d = p[g].y;
            }
        }
    }
    if (act)
        red4(out + (size_t)d * 40 + lane * 4, acc.x, acc.y, acc.z, acc.w);
}

// ---------------------------------------------------------------------------
// Launch: gemm1 overlaps the graph preamble on a second stream.
// ---------------------------------------------------------------------------
extern "C" void kernel_launch(void* const* d_in, const int* in_sizes, int n_in,
                              void* d_out, int out_size) {
    const float* x  = (const float*)d_in[0];
    const int*   ei = (const int*)d_in[1];
    const float* ew = (const float*)d_in[2];
    const float* W1 = (const float*)d_in[3];
    const float* b1 = (const float*)d_in[4];
    const float* W2 = (const float*)d_in[5];
    const float* b2 = (const float*)d_in[6];
    const float* W3 = (const float*)d_in[7];
    const float* b3 = (const float*)d_in[8];
    float* out = (float*)d_out;

    const int n = in_sizes[0] / 128;       // 50000
    const int e = in_sizes[2];             // 640000
    const int* src = ei;
    const int* dst = ei + e;

    int *count, *cursor, *part;
    int4* pack;
    float *dinv, *h, *agg1, *agg2, *h3;
    cudaGetSymbolAddress((void**)&count,  g_count);
    cudaGetSymbolAddress((void**)&dinv,   g_dinv);
    cudaGetSymbolAddress((void**)&part,   g_part);
    cudaGetSymbolAddress((void**)&cursor, g_cursor);
    cudaGetSymbolAddress((void**)&pack,   g_pack);
    cudaGetSymbolAddress((void**)&h,      g_h);
    cudaGetSymbolAddress((void**)&agg1,   g_agg1);
    cudaGetSymbolAddress((void**)&agg2,   g_agg2);
    cudaGetSymbolAddress((void**)&h3,     g_h3);

    static cudaStream_t s2 = nullptr;
    static cudaEvent_t evFork = nullptr, evG1 = nullptr;
    if (s2 == nullptr) {
        cudaStreamCreateWithFlags(&s2, cudaStreamNonBlocking);
        cudaEventCreateWithFlags(&evFork, cudaEventDisableTiming);
        cudaEventCreateWithFlags(&evG1, cudaEventDisableTiming);
    }

    const int nb_n = (n + 255) / 256;
    const int nb_e = (e + 255) / 256;
    const int nb_scan = (n + SCAN_CHUNK - 1) / SCAN_CHUNK;   // 49
    const int gemm_blocks = (n + 127) / 128;
    const int nw = (e + GRP - 1) / GRP;
    const int scat_blocks = (nw * 32 + 255) / 256;

    // Fork: gemm1 (graph-independent, H only) on s2
    cudaEventRecord(evFork, 0);
    cudaStreamWaitEvent(s2, evFork, 0);
    gemm128_kernel<false, false><<<gemm_blocks, 256, 0, s2>>>(
        x, W1, nullptr, nullptr, h, nullptr, n);
    cudaEventRecord(evG1, s2);

    // Preamble on main stream (concurrent with gemm1)
    zero_kernel<<<nb_n, 256>>>(count, dinv, n);
    hist_kernel<<<nb_e, 256>>>(dst, ew, count, dinv, e);
    partial_kernel<<<nb_scan, 256>>>(count, part, n);
    scanpart_kernel<<<1, 256>>>(part, nb_scan);
    scanfinal_kernel<<<nb_scan, 256>>>(count, part, dinv, cursor, n);
    fill_kernel<<<nb_e, 256>>>(src, dst, ew, dinv, cursor, pack, e);

    // Join, then layer-1 epilogue + scatter
    cudaStreamWaitEvent(0, evG1, 0);
    agg_init128<<<(n * 32 + 255) / 256, 256>>>(h, dinv, b1, agg1, n);
    scatter128_perm<<<scat_blocks, 256>>>(h, pack, agg1, e, nw);

    // Layer 2 (relu + fused epilogue)
    gemm128_kernel<true, true><<<gemm_blocks, 256>>>(agg1, W2, b2, dinv, h, agg2, n);
    scatter128_perm<<<scat_blocks, 256>>>(h, pack, agg2, e, nw);

    // Layer 3 (relu fused; scatter straight to d_out)
    static const int g40_smem = (64 * 129 + 128 * 40) * sizeof(float);
    cudaFuncSetAttribute(gemm40_kernel,
                         cudaFuncAttributeMaxDynamicSharedMemorySize, g40_smem);
    gemm40_kernel<<<(n + 63) / 64, 128, g40_smem>>>(agg2, W3, b3, dinv, h3, out, n);
    scatter40_perm<<<scat_blocks, 256>>>(h3, pack, out, e, nw);
}